// round 4
// baseline (speedup 1.0000x reference)
#include <cuda_runtime.h>
#include <cuda_bf16.h>
#include <cstdint>

// Problem constants
constexpr int T_DIM = 256;
constexpr int B_DIM = 256;
constexpr int IN_DIM = 1024;
constexpr int H_DIM = 1024;
constexpr int M1 = T_DIM * B_DIM;     // 65536 rows for phase-1 GEMM
constexpr int BH = B_DIM * H_DIM;     // one [B,H] slab

// Persistent-kernel step barrier: one counter per timestep.
__device__ int g_cnt[T_DIM];

constexpr int N_CTAS = 128;           // 4 M-tiles x 32 N-tiles
constexpr int BK_STAGE = 64;          // k per staging chunk
constexpr int N_STAGES = H_DIM / BK_STAGE;   // 16
constexpr int AS_STRIDE = 66;         // float2 stride (padded: bank-skew + 16B align)
// smem: Wh [1024][32] floats (128KB) + A dup double buffer 2*[64][66] float2
constexpr int WH_FLOATS = H_DIM * 32;                 // 32768 floats
constexpr int AS_F2_PER_BUF = BK_STAGE * AS_STRIDE;   // 4224 float2
constexpr int SMEM_BYTES = WH_FLOATS * 4 + 2 * AS_F2_PER_BUF * 8;  // 198656 B

// ---------------------------------------------------------------------------
// Packed f32x2 helpers (Blackwell FFMA2 — double-rate fp32)
// ---------------------------------------------------------------------------
__device__ __forceinline__ unsigned long long pack2(float lo, float hi) {
    unsigned long long r;
    asm("mov.b64 %0, {%1, %2};" : "=l"(r) : "f"(lo), "f"(hi));
    return r;
}
__device__ __forceinline__ unsigned long long ffma2(unsigned long long a,
                                                    unsigned long long b,
                                                    unsigned long long c) {
    unsigned long long d;
    asm("fma.rn.f32x2 %0, %1, %2, %3;" : "=l"(d) : "l"(a), "l"(b), "l"(c));
    return d;
}
__device__ __forceinline__ float2 unpack2(unsigned long long v) {
    float2 f;
    asm("mov.b64 {%0, %1}, %2;" : "=f"(f.x), "=f"(f.y) : "l"(v));
    return f;
}

// ---------------------------------------------------------------------------
// Reset kernel: zero the step counters (runs once per replay, before phase 2)
// ---------------------------------------------------------------------------
__global__ void reset_kernel() {
    if (threadIdx.x < T_DIM) g_cnt[threadIdx.x] = 0;
}

// ---------------------------------------------------------------------------
// Phase 1: xi[m, n] = sum_k x[m,k] * Wi[n,k] + bi[n]
// M=65536, N=1024, K=1024.  BM=BN=128, BK=8, 256 threads, 8x8 per thread.
// ---------------------------------------------------------------------------
__global__ __launch_bounds__(256) void gemm_xi_kernel(
    const float* __restrict__ A,     // x  [M1, IN]
    const float* __restrict__ Bw,    // Wi [H, IN]
    const float* __restrict__ bias,  // bi [H]
    float* __restrict__ C)           // xi -> d_out [M1, H]
{
    __shared__ float As[8][128];
    __shared__ float Bs[8][128];

    const int tid = threadIdx.x;
    const int m0 = blockIdx.y * 128;
    const int n0 = blockIdx.x * 128;
    const int tx = tid & 15;
    const int ty = tid >> 4;
    const int lr = tid >> 1;
    const int lc = (tid & 1) * 4;

    unsigned long long acc[8][4];
#pragma unroll
    for (int i = 0; i < 8; i++)
#pragma unroll
        for (int j = 0; j < 4; j++) acc[i][j] = 0ull;

    const float* aLoad = A + (size_t)(m0 + lr) * IN_DIM + lc;
    const float* bLoad = Bw + (size_t)(n0 + lr) * IN_DIM + lc;

    for (int k0 = 0; k0 < IN_DIM; k0 += 8) {
        float4 av = *reinterpret_cast<const float4*>(aLoad + k0);
        float4 bv = *reinterpret_cast<const float4*>(bLoad + k0);
        As[lc + 0][lr] = av.x; As[lc + 1][lr] = av.y;
        As[lc + 2][lr] = av.z; As[lc + 3][lr] = av.w;
        Bs[lc + 0][lr] = bv.x; Bs[lc + 1][lr] = bv.y;
        Bs[lc + 2][lr] = bv.z; Bs[lc + 3][lr] = bv.w;
        __syncthreads();

#pragma unroll
        for (int k = 0; k < 8; k++) {
            float4 a0 = *reinterpret_cast<const float4*>(&As[k][ty * 8]);
            float4 a1 = *reinterpret_cast<const float4*>(&As[k][ty * 8 + 4]);
            ulonglong2 b01 = *reinterpret_cast<const ulonglong2*>(&Bs[k][tx * 8]);
            ulonglong2 b23 = *reinterpret_cast<const ulonglong2*>(&Bs[k][tx * 8 + 4]);
            float a[8] = {a0.x, a0.y, a0.z, a0.w, a1.x, a1.y, a1.z, a1.w};
#pragma unroll
            for (int i = 0; i < 8; i++) {
                unsigned long long a2 = pack2(a[i], a[i]);
                acc[i][0] = ffma2(a2, b01.x, acc[i][0]);
                acc[i][1] = ffma2(a2, b01.y, acc[i][1]);
                acc[i][2] = ffma2(a2, b23.x, acc[i][2]);
                acc[i][3] = ffma2(a2, b23.y, acc[i][3]);
            }
        }
        __syncthreads();
    }

    float bb[8];
#pragma unroll
    for (int j = 0; j < 8; j++) bb[j] = bias[n0 + tx * 8 + j];

#pragma unroll
    for (int i = 0; i < 8; i++) {
        float c[8];
#pragma unroll
        for (int j = 0; j < 4; j++) {
            float2 v = unpack2(acc[i][j]);
            c[2 * j + 0] = v.x + bb[2 * j + 0];
            c[2 * j + 1] = v.y + bb[2 * j + 1];
        }
        float* cp = C + (size_t)(m0 + ty * 8 + i) * H_DIM + n0 + tx * 8;
        *reinterpret_cast<float4*>(cp + 0) = make_float4(c[0], c[1], c[2], c[3]);
        *reinterpret_cast<float4*>(cp + 4) = make_float4(c[4], c[5], c[6], c[7]);
    }
}

// ---------------------------------------------------------------------------
// Phase 2: persistent recurrence kernel, smem-staged A.
// Grid: 128 CTAs (4 M-tiles of 64 rows x 32 N-tiles of 32 cols), 256 threads.
// Per CTA, resident across all 256 steps: Wh slice [1024 k][32 n] (128 KB).
// Per step, per stage (64 k's): cooperatively load A[64 rows][64 k] from L2
// (coalesced, NON-redundant), store pre-duplicated (a,a) into double-buffered
// smem; inner loop: 1 LDS.128 (a) + 1 LDS.128 (b) + 4 FFMA2 per k per thread.
// Fused epilogue h = tanh(acc + xi + bh); device-wide barrier per step.
// ---------------------------------------------------------------------------
__global__ __launch_bounds__(256, 1) void rnn_persistent(
    const float* __restrict__ h0,
    const float* __restrict__ Wh,
    const float* __restrict__ bh,
    float* __restrict__ out)
{
    extern __shared__ float smem[];
    float* Bs = smem;                                        // [1024][32]
    float2* As2 = reinterpret_cast<float2*>(smem + WH_FLOATS); // 2 x [64][66]

    const int tid = threadIdx.x;
    const int n0 = blockIdx.x * 32;  // 32 n-tiles
    const int m0 = blockIdx.y * 64;  // 4 m-tiles

    // One-time: load Wh slice (rows n0..n0+31, all K) transposed to [k][n].
    for (int i = tid; i < 32 * (H_DIM / 4); i += 256) {
        const int n = i >> 8;
        const int kq = (i & 255) << 2;
        float4 w = *reinterpret_cast<const float4*>(Wh + (size_t)(n0 + n) * H_DIM + kq);
        Bs[(kq + 0) * 32 + n] = w.x;
        Bs[(kq + 1) * 32 + n] = w.y;
        Bs[(kq + 2) * 32 + n] = w.z;
        Bs[(kq + 3) * 32 + n] = w.w;
    }

    const int tx = tid & 7;    // cols c..c+3
    const int ty = tid >> 3;   // rows 2ty, 2ty+1
    const int c = n0 + 4 * tx;
    const int r0 = m0 + 2 * ty;

    // A-stage loader mapping: 1024 float4 per stage / 256 threads = 4 each.
    // e = tid + it*256 ; row = e>>4 (0..63), kq4 = e&15 (float4 within 64 k)
    const int l_r0  = tid >> 4;          // rows l_r0 + 16*it
    const int l_kq  = (tid & 15) * 4;    // k offset within stage

    const float4 bb = *reinterpret_cast<const float4*>(bh + c);
    __syncthreads();

    for (int t = 0; t < T_DIM; t++) {
        const float* hp = (t == 0) ? h0 : (out + (size_t)(t - 1) * BH);

        float4 pf[4];
        // Prologue: load stage 0 to regs, store dup to buffer 0
#pragma unroll
        for (int it = 0; it < 4; it++) {
            pf[it] = __ldcg(reinterpret_cast<const float4*>(
                hp + (size_t)(m0 + l_r0 + 16 * it) * H_DIM + l_kq));
        }
#pragma unroll
        for (int it = 0; it < 4; it++) {
            const int r = l_r0 + 16 * it;
            As2[(l_kq + 0) * AS_STRIDE + r] = make_float2(pf[it].x, pf[it].x);
            As2[(l_kq + 1) * AS_STRIDE + r] = make_float2(pf[it].y, pf[it].y);
            As2[(l_kq + 2) * AS_STRIDE + r] = make_float2(pf[it].z, pf[it].z);
            As2[(l_kq + 3) * AS_STRIDE + r] = make_float2(pf[it].w, pf[it].w);
        }
        __syncthreads();

        unsigned long long acc00 = 0ull, acc01 = 0ull;
        unsigned long long acc10 = 0ull, acc11 = 0ull;

        for (int s = 0; s < N_STAGES; s++) {
            const int buf = s & 1;
            const float2* aBuf = As2 + buf * AS_F2_PER_BUF;

            // Prefetch next stage (global -> regs), latency hidden by compute
            if (s + 1 < N_STAGES) {
#pragma unroll
                for (int it = 0; it < 4; it++) {
                    pf[it] = __ldcg(reinterpret_cast<const float4*>(
                        hp + (size_t)(m0 + l_r0 + 16 * it) * H_DIM
                           + (s + 1) * BK_STAGE + l_kq));
                }
            }

            // Compute this stage: 64 k's
            const int kglob = s * BK_STAGE;
#pragma unroll 16
            for (int k = 0; k < BK_STAGE; k++) {
                ulonglong2 aa = *reinterpret_cast<const ulonglong2*>(
                    &aBuf[k * AS_STRIDE + 2 * ty]);
                ulonglong2 b2 = *reinterpret_cast<const ulonglong2*>(
                    &Bs[(kglob + k) * 32 + 4 * tx]);
                acc00 = ffma2(aa.x, b2.x, acc00);
                acc01 = ffma2(aa.x, b2.y, acc01);
                acc10 = ffma2(aa.y, b2.x, acc10);
                acc11 = ffma2(aa.y, b2.y, acc11);
            }
            __syncthreads();

            // Store prefetched regs into the other buffer
            if (s + 1 < N_STAGES) {
                float2* nBuf = As2 + (buf ^ 1) * AS_F2_PER_BUF;
#pragma unroll
                for (int it = 0; it < 4; it++) {
                    const int r = l_r0 + 16 * it;
                    nBuf[(l_kq + 0) * AS_STRIDE + r] = make_float2(pf[it].x, pf[it].x);
                    nBuf[(l_kq + 1) * AS_STRIDE + r] = make_float2(pf[it].y, pf[it].y);
                    nBuf[(l_kq + 2) * AS_STRIDE + r] = make_float2(pf[it].z, pf[it].z);
                    nBuf[(l_kq + 3) * AS_STRIDE + r] = make_float2(pf[it].w, pf[it].w);
                }
                __syncthreads();
            }
        }

        // Fused epilogue: h = tanh(acc + xi + bh), in place over xi
        float* xo = out + (size_t)t * BH;
        float* p0 = xo + (size_t)r0 * H_DIM + c;
        float* p1 = p0 + H_DIM;
        float4 x0 = __ldcg(reinterpret_cast<const float4*>(p0));
        float4 x1 = __ldcg(reinterpret_cast<const float4*>(p1));

        float2 u00 = unpack2(acc00), u01 = unpack2(acc01);
        float2 u10 = unpack2(acc10), u11 = unpack2(acc11);

        float4 o0, o1;
        o0.x = tanhf(u00.x + x0.x + bb.x);
        o0.y = tanhf(u00.y + x0.y + bb.y);
        o0.z = tanhf(u01.x + x0.z + bb.z);
        o0.w = tanhf(u01.y + x0.w + bb.w);
        o1.x = tanhf(u10.x + x1.x + bb.x);
        o1.y = tanhf(u10.y + x1.y + bb.y);
        o1.z = tanhf(u11.x + x1.z + bb.z);
        o1.w = tanhf(u11.y + x1.w + bb.w);

        *reinterpret_cast<float4*>(p0) = o0;
        *reinterpret_cast<float4*>(p1) = o1;

        // Device-wide step barrier (skip after last step)
        if (t + 1 < T_DIM) {
            __syncthreads();
            __threadfence();
            if (tid == 0) {
                atomicAdd(&g_cnt[t], 1);
                volatile int* p = &g_cnt[t];
                while (*p < N_CTAS) { }
            }
            __syncthreads();
            __threadfence();
        }
    }
}

// ---------------------------------------------------------------------------
// Launch
// inputs: 0=x [T,B,IN], 1=h [B,H], 2=Wi_w [H,IN], 3=Wi_b [H],
//         4=Wh_w [H,H], 5=Wh_b [H];  output: hiddens [T,B,H]
// ---------------------------------------------------------------------------
extern "C" void kernel_launch(void* const* d_in, const int* in_sizes, int n_in,
                              void* d_out, int out_size) {
    const float* x   = (const float*)d_in[0];
    const float* h0  = (const float*)d_in[1];
    const float* Wi  = (const float*)d_in[2];
    const float* bi  = (const float*)d_in[3];
    const float* Wh  = (const float*)d_in[4];
    const float* bh  = (const float*)d_in[5];
    float* out = (float*)d_out;

    static bool attr_set = false;
    if (!attr_set) {
        cudaFuncSetAttribute(rnn_persistent,
                             cudaFuncAttributeMaxDynamicSharedMemorySize,
                             SMEM_BYTES);
        attr_set = true;
    }

    // Reset step-barrier counters (each call / replay)
    reset_kernel<<<1, 256>>>();

    // Phase 1: xi for all timesteps, written straight into d_out
    gemm_xi_kernel<<<dim3(H_DIM / 128, M1 / 128), 256>>>(x, Wi, bi, out);

    // Phase 2: persistent recurrence (Wh resident in smem across all steps)
    rnn_persistent<<<dim3(32, 4), 256, SMEM_BYTES>>>(h0, Wh, bh, out);
}

// round 5
// speedup vs baseline: 2.2885x; 2.2885x over previous
#include <cuda_runtime.h>
#include <cuda_bf16.h>
#include <cstdint>

// Problem constants
constexpr int T_DIM = 256;
constexpr int B_DIM = 256;
constexpr int IN_DIM = 1024;
constexpr int H_DIM = 1024;
constexpr int M1 = T_DIM * B_DIM;     // 65536 rows for phase-1 GEMM
constexpr int BH = B_DIM * H_DIM;     // one [B,H] slab

// Persistent-kernel step barrier: one counter per timestep.
__device__ int g_cnt[T_DIM];

constexpr int N_CTAS = 128;           // 4 M-tiles x 32 N-tiles
constexpr int SMEM_BYTES = H_DIM * 32 * 4;   // Wh slice [1024][32] = 128KB
constexpr int DEPTH = 8;              // A-prefetch ring depth (chunks of 4 k)

// ---------------------------------------------------------------------------
// Packed f32x2 helpers (Blackwell FFMA2 — double-rate fp32)
// ---------------------------------------------------------------------------
__device__ __forceinline__ unsigned long long pack2(float lo, float hi) {
    unsigned long long r;
    asm("mov.b64 %0, {%1, %2};" : "=l"(r) : "f"(lo), "f"(hi));
    return r;
}
__device__ __forceinline__ unsigned long long ffma2(unsigned long long a,
                                                    unsigned long long b,
                                                    unsigned long long c) {
    unsigned long long d;
    asm("fma.rn.f32x2 %0, %1, %2, %3;" : "=l"(d) : "l"(a), "l"(b), "l"(c));
    return d;
}
__device__ __forceinline__ float2 unpack2(unsigned long long v) {
    float2 f;
    asm("mov.b64 {%0, %1}, %2;" : "=f"(f.x), "=f"(f.y) : "l"(v));
    return f;
}

// ---------------------------------------------------------------------------
// Reset kernel: zero the step counters (runs once per replay, before phase 2)
// ---------------------------------------------------------------------------
__global__ void reset_kernel() {
    if (threadIdx.x < T_DIM) g_cnt[threadIdx.x] = 0;
}

// ---------------------------------------------------------------------------
// Phase 1: xi[m, n] = sum_k x[m,k] * Wi[n,k] + bi[n]
// M=65536, N=1024, K=1024.  BM=BN=128, BK=8, 256 threads, 8x8 per thread.
// ---------------------------------------------------------------------------
__global__ __launch_bounds__(256) void gemm_xi_kernel(
    const float* __restrict__ A,     // x  [M1, IN]
    const float* __restrict__ Bw,    // Wi [H, IN]
    const float* __restrict__ bias,  // bi [H]
    float* __restrict__ C)           // xi -> d_out [M1, H]
{
    __shared__ float As[8][128];
    __shared__ float Bs[8][128];

    const int tid = threadIdx.x;
    const int m0 = blockIdx.y * 128;
    const int n0 = blockIdx.x * 128;
    const int tx = tid & 15;
    const int ty = tid >> 4;
    const int lr = tid >> 1;
    const int lc = (tid & 1) * 4;

    unsigned long long acc[8][4];
#pragma unroll
    for (int i = 0; i < 8; i++)
#pragma unroll
        for (int j = 0; j < 4; j++) acc[i][j] = 0ull;

    const float* aLoad = A + (size_t)(m0 + lr) * IN_DIM + lc;
    const float* bLoad = Bw + (size_t)(n0 + lr) * IN_DIM + lc;

    for (int k0 = 0; k0 < IN_DIM; k0 += 8) {
        float4 av = *reinterpret_cast<const float4*>(aLoad + k0);
        float4 bv = *reinterpret_cast<const float4*>(bLoad + k0);
        As[lc + 0][lr] = av.x; As[lc + 1][lr] = av.y;
        As[lc + 2][lr] = av.z; As[lc + 3][lr] = av.w;
        Bs[lc + 0][lr] = bv.x; Bs[lc + 1][lr] = bv.y;
        Bs[lc + 2][lr] = bv.z; Bs[lc + 3][lr] = bv.w;
        __syncthreads();

#pragma unroll
        for (int k = 0; k < 8; k++) {
            float4 a0 = *reinterpret_cast<const float4*>(&As[k][ty * 8]);
            float4 a1 = *reinterpret_cast<const float4*>(&As[k][ty * 8 + 4]);
            ulonglong2 b01 = *reinterpret_cast<const ulonglong2*>(&Bs[k][tx * 8]);
            ulonglong2 b23 = *reinterpret_cast<const ulonglong2*>(&Bs[k][tx * 8 + 4]);
            float a[8] = {a0.x, a0.y, a0.z, a0.w, a1.x, a1.y, a1.z, a1.w};
#pragma unroll
            for (int i = 0; i < 8; i++) {
                unsigned long long a2 = pack2(a[i], a[i]);
                acc[i][0] = ffma2(a2, b01.x, acc[i][0]);
                acc[i][1] = ffma2(a2, b01.y, acc[i][1]);
                acc[i][2] = ffma2(a2, b23.x, acc[i][2]);
                acc[i][3] = ffma2(a2, b23.y, acc[i][3]);
            }
        }
        __syncthreads();
    }

    float bb[8];
#pragma unroll
    for (int j = 0; j < 8; j++) bb[j] = bias[n0 + tx * 8 + j];

#pragma unroll
    for (int i = 0; i < 8; i++) {
        float c[8];
#pragma unroll
        for (int j = 0; j < 4; j++) {
            float2 v = unpack2(acc[i][j]);
            c[2 * j + 0] = v.x + bb[2 * j + 0];
            c[2 * j + 1] = v.y + bb[2 * j + 1];
        }
        float* cp = C + (size_t)(m0 + ty * 8 + i) * H_DIM + n0 + tx * 8;
        *reinterpret_cast<float4*>(cp + 0) = make_float4(c[0], c[1], c[2], c[3]);
        *reinterpret_cast<float4*>(cp + 4) = make_float4(c[4], c[5], c[6], c[7]);
    }
}

// ---------------------------------------------------------------------------
// Phase 2: persistent recurrence kernel (R3 structure + deep prefetch ring).
// Grid: 128 CTAs (4 M-tiles of 64 rows x 32 N-tiles of 32 cols), 256 threads.
// Wh slice [1024 k][32 n] resident in 128KB smem across all 256 steps.
// Per step: A (2 rows/thread) streamed from L2 via 8-deep register ring of
// float4 chunks (32 k's in flight -> covers L2/DRAM latency); B via one
// LDS.128 per k (intra-warp broadcast, conflict-free); 4 FFMA2 + 2 MOV per k.
// Fused epilogue h = tanh(acc + xi + bh); device-wide sense barrier per step.
// ---------------------------------------------------------------------------
__global__ __launch_bounds__(256, 1) void rnn_persistent(
    const float* __restrict__ h0,
    const float* __restrict__ Wh,
    const float* __restrict__ bh,
    float* __restrict__ out)
{
    extern __shared__ float Bs[];  // [1024][32] : Bs[k*32 + n]

    const int tid = threadIdx.x;
    const int n0 = blockIdx.x * 32;  // 32 n-tiles
    const int m0 = blockIdx.y * 64;  // 4 m-tiles

    // One-time: load Wh slice (rows n0..n0+31, all K) transposed to [k][n].
    for (int i = tid; i < 32 * (H_DIM / 4); i += 256) {
        const int n = i >> 8;
        const int kq = (i & 255) << 2;
        float4 w = *reinterpret_cast<const float4*>(Wh + (size_t)(n0 + n) * H_DIM + kq);
        Bs[(kq + 0) * 32 + n] = w.x;
        Bs[(kq + 1) * 32 + n] = w.y;
        Bs[(kq + 2) * 32 + n] = w.z;
        Bs[(kq + 3) * 32 + n] = w.w;
    }

    const int tx = tid & 7;    // cols c..c+3
    const int ty = tid >> 3;   // rows 2ty, 2ty+1
    const int c = n0 + 4 * tx;
    const int r0 = m0 + 2 * ty;

    const float4 bb = *reinterpret_cast<const float4*>(bh + c);
    __syncthreads();

    for (int t = 0; t < T_DIM; t++) {
        const float* hp = (t == 0) ? h0 : (out + (size_t)(t - 1) * BH);
        const float* a0p = hp + (size_t)r0 * H_DIM;
        const float* a1p = a0p + H_DIM;

        // Hoist epilogue xi loads: latency hides under the k loop.
        float* xo = out + (size_t)t * BH;
        float* p0 = xo + (size_t)r0 * H_DIM + c;
        float* p1 = p0 + H_DIM;
        const float4 x0 = __ldcg(reinterpret_cast<const float4*>(p0));
        const float4 x1 = __ldcg(reinterpret_cast<const float4*>(p1));

        unsigned long long acc00 = 0ull, acc01 = 0ull;
        unsigned long long acc10 = 0ull, acc11 = 0ull;

        // Prefetch ring: DEPTH chunks of 4 k's per row, all in flight.
        float4 bufA[DEPTH], bufB[DEPTH];
#pragma unroll
        for (int d = 0; d < DEPTH; d++) {
            bufA[d] = __ldcg(reinterpret_cast<const float4*>(a0p + 4 * d));
            bufB[d] = __ldcg(reinterpret_cast<const float4*>(a1p + 4 * d));
        }

#pragma unroll 8
        for (int s = 0; s < H_DIM / 4; s++) {
            const int d = s & (DEPTH - 1);
            const float4 a0 = bufA[d];
            const float4 a1 = bufB[d];
            if (s + DEPTH < H_DIM / 4) {
                bufA[d] = __ldcg(reinterpret_cast<const float4*>(
                    a0p + 4 * (s + DEPTH)));
                bufB[d] = __ldcg(reinterpret_cast<const float4*>(
                    a1p + 4 * (s + DEPTH)));
            }
            const float a0v[4] = {a0.x, a0.y, a0.z, a0.w};
            const float a1v[4] = {a1.x, a1.y, a1.z, a1.w};
#pragma unroll
            for (int j = 0; j < 4; j++) {
                ulonglong2 b2 = *reinterpret_cast<const ulonglong2*>(
                    &Bs[(4 * s + j) * 32 + 4 * tx]);
                unsigned long long pa0 = pack2(a0v[j], a0v[j]);
                unsigned long long pa1 = pack2(a1v[j], a1v[j]);
                acc00 = ffma2(pa0, b2.x, acc00);
                acc01 = ffma2(pa0, b2.y, acc01);
                acc10 = ffma2(pa1, b2.x, acc10);
                acc11 = ffma2(pa1, b2.y, acc11);
            }
        }

        // Fused epilogue: h = tanh(acc + xi + bh), in place over xi
        float2 u00 = unpack2(acc00), u01 = unpack2(acc01);
        float2 u10 = unpack2(acc10), u11 = unpack2(acc11);

        float4 o0, o1;
        o0.x = tanhf(u00.x + x0.x + bb.x);
        o0.y = tanhf(u00.y + x0.y + bb.y);
        o0.z = tanhf(u01.x + x0.z + bb.z);
        o0.w = tanhf(u01.y + x0.w + bb.w);
        o1.x = tanhf(u10.x + x1.x + bb.x);
        o1.y = tanhf(u10.y + x1.y + bb.y);
        o1.z = tanhf(u11.x + x1.z + bb.z);
        o1.w = tanhf(u11.y + x1.w + bb.w);

        *reinterpret_cast<float4*>(p0) = o0;
        *reinterpret_cast<float4*>(p1) = o1;

        // Device-wide step barrier (skip after last step)
        if (t + 1 < T_DIM) {
            __syncthreads();          // all CTA stores issued
            __threadfence();          // release: visible device-wide
            if (tid == 0) {
                atomicAdd(&g_cnt[t], 1);
                volatile int* p = &g_cnt[t];
                while (*p < N_CTAS) { }
            }
            __syncthreads();
            __threadfence();          // acquire: observe other CTAs' h writes
        }
    }
}

// ---------------------------------------------------------------------------
// Launch
// inputs: 0=x [T,B,IN], 1=h [B,H], 2=Wi_w [H,IN], 3=Wi_b [H],
//         4=Wh_w [H,H], 5=Wh_b [H];  output: hiddens [T,B,H]
// ---------------------------------------------------------------------------
extern "C" void kernel_launch(void* const* d_in, const int* in_sizes, int n_in,
                              void* d_out, int out_size) {
    const float* x   = (const float*)d_in[0];
    const float* h0  = (const float*)d_in[1];
    const float* Wi  = (const float*)d_in[2];
    const float* bi  = (const float*)d_in[3];
    const float* Wh  = (const float*)d_in[4];
    const float* bh  = (const float*)d_in[5];
    float* out = (float*)d_out;

    static bool attr_set = false;
    if (!attr_set) {
        cudaFuncSetAttribute(rnn_persistent,
                             cudaFuncAttributeMaxDynamicSharedMemorySize,
                             SMEM_BYTES);
        attr_set = true;
    }

    // Reset step-barrier counters (each call / replay)
    reset_kernel<<<1, 256>>>();

    // Phase 1: xi for all timesteps, written straight into d_out
    gemm_xi_kernel<<<dim3(H_DIM / 128, M1 / 128), 256>>>(x, Wi, bi, out);

    // Phase 2: persistent recurrence (Wh resident in smem across all steps)
    rnn_persistent<<<dim3(32, 4), 256, SMEM_BYTES>>>(h0, Wh, bh, out);
}

// round 7
// speedup vs baseline: 3.8371x; 1.6767x over previous
#include <cuda_runtime.h>
#include <cuda_bf16.h>
#include <cstdint>

// Problem constants
constexpr int T_DIM = 256;
constexpr int B_DIM = 256;
constexpr int IN_DIM = 1024;
constexpr int H_DIM = 1024;
constexpr int M1 = T_DIM * B_DIM;
constexpr int BH = B_DIM * H_DIM;

// ---------------------------------------------------------------------------
// Device globals (static allocations - allowed)
// ---------------------------------------------------------------------------
__device__ int g_cnt[T_DIM];                       // per-step barrier counters
__device__ __nv_bfloat16 g_Wh_hi[H_DIM * H_DIM];   // Wh split hi
__device__ __nv_bfloat16 g_Wh_lo[H_DIM * H_DIM];   // Wh split lo
__device__ __nv_bfloat16 g_h_hi[2][BH];            // h split hi (step parity)
__device__ __nv_bfloat16 g_h_lo[2][BH];            // h split lo

constexpr int N_CTAS = 128;    // 32 n-tiles x 4 m-tiles

// Shared memory layout (bytes) for the persistent kernel
// B (Wh slice) resident: [32 n][1032 k] bf16 per half (pad 8 -> 2064B rows)
constexpr int B_ROW_BYTES = 1032 * 2;                  // 2064
constexpr int SM_BHI = 0;
constexpr int SM_BLO = SM_BHI + 32 * B_ROW_BYTES;      // 66048
// A chunks: [64 rows][136 k] bf16 (pad 8 -> 272B rows), double buffered, hi+lo
constexpr int A_ROW_BYTES = 136 * 2;                   // 272
constexpr int A_BUF = 64 * A_ROW_BYTES;                // 17408
constexpr int SM_A_HI = SM_BLO + 32 * B_ROW_BYTES;     // 132096
constexpr int SM_A_LO = SM_A_HI + 2 * A_BUF;           // 166912
constexpr int SM_RED = SM_A_HI;                        // reuse buf0-hi for k-reduction
constexpr int SMEM_P2 = SM_A_LO + 2 * A_BUF;           // 201728

// ---------------------------------------------------------------------------
// PTX helpers (baseline sm_103-legal: ldmatrix + mma.sync HMMA path)
// ---------------------------------------------------------------------------
__device__ __forceinline__ uint32_t smem_to_u32(const void* p) {
    uint32_t a;
    asm("{ .reg .u64 t; cvta.to.shared.u64 t, %1; cvt.u32.u64 %0, t; }"
        : "=r"(a) : "l"(p));
    return a;
}
__device__ __forceinline__ void ldsm4(uint32_t r[4], uint32_t addr) {
    asm volatile("ldmatrix.sync.aligned.m8n8.x4.shared.b16 {%0,%1,%2,%3}, [%4];"
                 : "=r"(r[0]), "=r"(r[1]), "=r"(r[2]), "=r"(r[3]) : "r"(addr));
}
__device__ __forceinline__ void mma_bf16(float d[4], const uint32_t a[4],
                                         const uint32_t b[2]) {
    asm volatile(
        "mma.sync.aligned.m16n8k16.row.col.f32.bf16.bf16.f32 "
        "{%0,%1,%2,%3}, {%4,%5,%6,%7}, {%8,%9}, {%0,%1,%2,%3};"
        : "+f"(d[0]), "+f"(d[1]), "+f"(d[2]), "+f"(d[3])
        : "r"(a[0]), "r"(a[1]), "r"(a[2]), "r"(a[3]), "r"(b[0]), "r"(b[1]));
}

// ---------------------------------------------------------------------------
// Packed f32x2 helpers (phase-1 GEMM)
// ---------------------------------------------------------------------------
__device__ __forceinline__ unsigned long long pack2(float lo, float hi) {
    unsigned long long r;
    asm("mov.b64 %0, {%1, %2};" : "=l"(r) : "f"(lo), "f"(hi));
    return r;
}
__device__ __forceinline__ unsigned long long ffma2(unsigned long long a,
                                                    unsigned long long b,
                                                    unsigned long long c) {
    unsigned long long d;
    asm("fma.rn.f32x2 %0, %1, %2, %3;" : "=l"(d) : "l"(a), "l"(b), "l"(c));
    return d;
}
__device__ __forceinline__ float2 unpack2(unsigned long long v) {
    float2 f;
    asm("mov.b64 {%0, %1}, %2;" : "=f"(f.x), "=f"(f.y) : "l"(v));
    return f;
}

// ---------------------------------------------------------------------------
// Setup kernels
// ---------------------------------------------------------------------------
__global__ void reset_kernel() {
    if (threadIdx.x < T_DIM) g_cnt[threadIdx.x] = 0;
}

__global__ __launch_bounds__(256) void split_wh_kernel(const float* __restrict__ W) {
    int i = (blockIdx.x * 256 + threadIdx.x) * 4;
    float4 w = *reinterpret_cast<const float4*>(W + i);
#pragma unroll
    for (int j = 0; j < 4; j++) {
        float v = (&w.x)[j];
        __nv_bfloat16 hi = __float2bfloat16(v);
        float r = v - __bfloat162float(hi);
        g_Wh_hi[i + j] = hi;
        g_Wh_lo[i + j] = __float2bfloat16(r);
    }
}

__global__ __launch_bounds__(256) void split_h0_kernel(const float* __restrict__ h0) {
    int i = (blockIdx.x * 256 + threadIdx.x) * 4;
    float4 v4 = *reinterpret_cast<const float4*>(h0 + i);
#pragma unroll
    for (int j = 0; j < 4; j++) {
        float v = (&v4.x)[j];
        __nv_bfloat16 hi = __float2bfloat16(v);
        float r = v - __bfloat162float(hi);
        g_h_hi[0][i + j] = hi;
        g_h_lo[0][i + j] = __float2bfloat16(r);
    }
}

// ---------------------------------------------------------------------------
// Phase 1: xi = x @ Wi^T + bi (FFMA2 SGEMM, unchanged - proven correct)
// ---------------------------------------------------------------------------
__global__ __launch_bounds__(256) void gemm_xi_kernel(
    const float* __restrict__ A, const float* __restrict__ Bw,
    const float* __restrict__ bias, float* __restrict__ C)
{
    __shared__ float As[8][128];
    __shared__ float Bs[8][128];

    const int tid = threadIdx.x;
    const int m0 = blockIdx.y * 128;
    const int n0 = blockIdx.x * 128;
    const int tx = tid & 15;
    const int ty = tid >> 4;
    const int lr = tid >> 1;
    const int lc = (tid & 1) * 4;

    unsigned long long acc[8][4];
#pragma unroll
    for (int i = 0; i < 8; i++)
#pragma unroll
        for (int j = 0; j < 4; j++) acc[i][j] = 0ull;

    const float* aLoad = A + (size_t)(m0 + lr) * IN_DIM + lc;
    const float* bLoad = Bw + (size_t)(n0 + lr) * IN_DIM + lc;

    for (int k0 = 0; k0 < IN_DIM; k0 += 8) {
        float4 av = *reinterpret_cast<const float4*>(aLoad + k0);
        float4 bv = *reinterpret_cast<const float4*>(bLoad + k0);
        As[lc + 0][lr] = av.x; As[lc + 1][lr] = av.y;
        As[lc + 2][lr] = av.z; As[lc + 3][lr] = av.w;
        Bs[lc + 0][lr] = bv.x; Bs[lc + 1][lr] = bv.y;
        Bs[lc + 2][lr] = bv.z; Bs[lc + 3][lr] = bv.w;
        __syncthreads();

#pragma unroll
        for (int k = 0; k < 8; k++) {
            float4 a0 = *reinterpret_cast<const float4*>(&As[k][ty * 8]);
            float4 a1 = *reinterpret_cast<const float4*>(&As[k][ty * 8 + 4]);
            ulonglong2 b01 = *reinterpret_cast<const ulonglong2*>(&Bs[k][tx * 8]);
            ulonglong2 b23 = *reinterpret_cast<const ulonglong2*>(&Bs[k][tx * 8 + 4]);
            float a[8] = {a0.x, a0.y, a0.z, a0.w, a1.x, a1.y, a1.z, a1.w};
#pragma unroll
            for (int i = 0; i < 8; i++) {
                unsigned long long a2 = pack2(a[i], a[i]);
                acc[i][0] = ffma2(a2, b01.x, acc[i][0]);
                acc[i][1] = ffma2(a2, b01.y, acc[i][1]);
                acc[i][2] = ffma2(a2, b23.x, acc[i][2]);
                acc[i][3] = ffma2(a2, b23.y, acc[i][3]);
            }
        }
        __syncthreads();
    }

    float bb[8];
#pragma unroll
    for (int j = 0; j < 8; j++) bb[j] = bias[n0 + tx * 8 + j];

#pragma unroll
    for (int i = 0; i < 8; i++) {
        float c[8];
#pragma unroll
        for (int j = 0; j < 4; j++) {
            float2 v = unpack2(acc[i][j]);
            c[2 * j + 0] = v.x + bb[2 * j + 0];
            c[2 * j + 1] = v.y + bb[2 * j + 1];
        }
        float* cp = C + (size_t)(m0 + ty * 8 + i) * H_DIM + n0 + tx * 8;
        *reinterpret_cast<float4*>(cp + 0) = make_float4(c[0], c[1], c[2], c[3]);
        *reinterpret_cast<float4*>(cp + 4) = make_float4(c[4], c[5], c[6], c[7]);
    }
}

// ---------------------------------------------------------------------------
// Phase 2: persistent HMMA recurrence (mma.sync m16n8k16 bf16, bf16x3 split).
// 128 CTAs (32 n-tiles x 4 m-tiles of 64x32), 256 threads (8 warps).
// Warp w: m16-tile = w%4, k-half (within each 128-chunk) = w/4, n = all 32.
// Per k16 step per warp: 6 ldmatrix.x4 + 12 mma (hi*hi + lo*hi + hi*lo).
// Wh hi/lo slice resident in padded smem; A (h hi/lo) staged in k=128 chunks,
// double buffered, conflict-free STS. Cross-warp k-reduction via smem, fused
// tanh epilogue writes fp32 out + bf16 hi/lo h. Device-wide barrier per step.
// ---------------------------------------------------------------------------
__global__ __launch_bounds__(256, 1) void rnn_hmma(
    const float* __restrict__ bh, float* __restrict__ out)
{
    extern __shared__ char sm[];
    const uint32_t sb = smem_to_u32(sm);
    const int tid = threadIdx.x;
    const int wid = tid >> 5;
    const int lane = tid & 31;
    const int n0 = blockIdx.x * 32;
    const int m0 = blockIdx.y * 64;
    const int mt = wid & 3;     // m16 tile
    const int kh = wid >> 2;    // k-half within chunk
    const int g = lane >> 2;
    const int tig = lane & 3;

    // One-time: load resident Wh hi/lo slice [32n][1024k] into padded smem.
    for (int i = 0; i < 16; i++) {
        int u = tid + 256 * i;               // 0..4095 uint4 units per half
        int n = u >> 7;                      // 0..31
        int kq = (u & 127) * 8;              // 0..1016
        uint4 vh = *reinterpret_cast<const uint4*>(&g_Wh_hi[(size_t)(n0 + n) * H_DIM + kq]);
        uint4 vl = *reinterpret_cast<const uint4*>(&g_Wh_lo[(size_t)(n0 + n) * H_DIM + kq]);
        *reinterpret_cast<uint4*>(sm + SM_BHI + n * B_ROW_BYTES + kq * 2) = vh;
        *reinterpret_cast<uint4*>(sm + SM_BLO + n * B_ROW_BYTES + kq * 2) = vl;
    }
    __syncthreads();

    // ldmatrix lane-address components.
    // A x4 tiles: {m0-7 k0-7, m8-15 k0-7, m0-7 k8-15, m8-15 k8-15}
    const uint32_t aByte =
        (uint32_t)((mt * 16 + (lane & 7) + ((lane >> 3) & 1) * 8) * A_ROW_BYTES
                   + ((lane >> 4) & 1) * 16);
    // B x4 tiles for an n16 group: {n0-7 k0-7, n0-7 k8-15, n8-15 k0-7, n8-15 k8-15}
    const uint32_t bRow = (uint32_t)((lane & 7) + ((lane >> 4) & 1) * 8);
    const uint32_t bKof = ((lane >> 3) & 1) * 16;
    const uint32_t bByte0 = bRow * B_ROW_BYTES + bKof;
    const uint32_t bByte1 = (bRow + 16) * B_ROW_BYTES + bKof;

    float2 bb[4];
#pragma unroll
    for (int nt = 0; nt < 4; nt++)
        bb[nt] = *reinterpret_cast<const float2*>(&bh[n0 + nt * 8 + tig * 2]);

    for (int t = 0; t < T_DIM; t++) {
        const int pb = t & 1;
        const __nv_bfloat16* Ah = g_h_hi[pb] + (size_t)m0 * H_DIM;
        const __nv_bfloat16* Al = g_h_lo[pb] + (size_t)m0 * H_DIM;

        float d[4][4];
#pragma unroll
        for (int nt = 0; nt < 4; nt++)
#pragma unroll
            for (int e = 0; e < 4; e++) d[nt][e] = 0.0f;

        // Prefetch chunk 0 (A [64 rows][128 k] hi+lo, coalesced uint4)
        uint4 rh[4], rl[4];
#pragma unroll
        for (int i = 0; i < 4; i++) {
            int u = tid + 256 * i;           // 0..1023
            int row = u >> 4;                // 0..63
            int kq = (u & 15) * 8;           // 0..120
            rh[i] = *reinterpret_cast<const uint4*>(&Ah[(size_t)row * H_DIM + kq]);
            rl[i] = *reinterpret_cast<const uint4*>(&Al[(size_t)row * H_DIM + kq]);
        }

        for (int kc = 0; kc < 8; kc++) {
            const int buf = kc & 1;
            char* ah_s = sm + SM_A_HI + buf * A_BUF;
            char* al_s = sm + SM_A_LO + buf * A_BUF;
            // STS (conflict-free: contiguous 16B within padded rows)
#pragma unroll
            for (int i = 0; i < 4; i++) {
                int u = tid + 256 * i;
                int row = u >> 4;
                int kq = (u & 15) * 8;
                *reinterpret_cast<uint4*>(ah_s + row * A_ROW_BYTES + kq * 2) = rh[i];
                *reinterpret_cast<uint4*>(al_s + row * A_ROW_BYTES + kq * 2) = rl[i];
            }
            __syncthreads();
            // Prefetch next chunk (latency hidden by the mma work below)
            if (kc + 1 < 8) {
                const int kb = (kc + 1) * 128;
#pragma unroll
                for (int i = 0; i < 4; i++) {
                    int u = tid + 256 * i;
                    int row = u >> 4;
                    int kq = (u & 15) * 8;
                    rh[i] = *reinterpret_cast<const uint4*>(&Ah[(size_t)row * H_DIM + kb + kq]);
                    rl[i] = *reinterpret_cast<const uint4*>(&Al[(size_t)row * H_DIM + kb + kq]);
                }
            }
            // Compute this chunk: 4 k16 steps on this warp's k-half
            const uint32_t ahB = sb + SM_A_HI + buf * A_BUF + aByte + kh * 128;
            const uint32_t alB = sb + SM_A_LO + buf * A_BUF + aByte + kh * 128;
            const uint32_t bkB = (uint32_t)((kc * 128 + kh * 64) * 2);
#pragma unroll
            for (int ks = 0; ks < 4; ks++) {
                uint32_t a_hi[4], a_lo[4], b_h[8], b_l[8];
                ldsm4(a_hi, ahB + ks * 32);
                ldsm4(a_lo, alB + ks * 32);
                ldsm4(b_h,     sb + SM_BHI + bByte0 + bkB + ks * 32);
                ldsm4(b_h + 4, sb + SM_BHI + bByte1 + bkB + ks * 32);
                ldsm4(b_l,     sb + SM_BLO + bByte0 + bkB + ks * 32);
                ldsm4(b_l + 4, sb + SM_BLO + bByte1 + bkB + ks * 32);
#pragma unroll
                for (int nt = 0; nt < 4; nt++) {
                    const uint32_t* ph = &b_h[(nt >> 1) * 4 + (nt & 1) * 2];
                    const uint32_t* pl = &b_l[(nt >> 1) * 4 + (nt & 1) * 2];
                    mma_bf16(d[nt], a_hi, ph);
                    mma_bf16(d[nt], a_lo, ph);
                    mma_bf16(d[nt], a_hi, pl);
                }
            }
        }
        __syncthreads();

        // Cross-warp k-reduction: k-half 1 publishes partials into smem.
        if (kh == 1) {
#pragma unroll
            for (int nt = 0; nt < 4; nt++)
#pragma unroll
                for (int rp = 0; rp < 2; rp++) {
                    const int row = mt * 16 + g + rp * 8;
                    *reinterpret_cast<float2*>(
                        sm + SM_RED + row * 136 + (nt * 8 + tig * 2) * 4) =
                        make_float2(d[nt][rp * 2], d[nt][rp * 2 + 1]);
                }
        }
        __syncthreads();

        if (kh == 0) {
            const int pb1 = pb ^ 1;
            float* outT = out + (size_t)t * BH;
#pragma unroll
            for (int nt = 0; nt < 4; nt++) {
                const int col = n0 + nt * 8 + tig * 2;
#pragma unroll
                for (int rp = 0; rp < 2; rp++) {
                    const int lrow = mt * 16 + g + rp * 8;
                    const int row = m0 + lrow;
                    float2 p = *reinterpret_cast<const float2*>(
                        sm + SM_RED + lrow * 136 + (nt * 8 + tig * 2) * 4);
                    float sx = d[nt][rp * 2] + p.x;
                    float sy = d[nt][rp * 2 + 1] + p.y;
                    float* op = outT + (size_t)row * H_DIM + col;
                    float2 xv = *reinterpret_cast<const float2*>(op);
                    float ox = tanhf(sx + xv.x + bb[nt].x);
                    float oy = tanhf(sy + xv.y + bb[nt].y);
                    *reinterpret_cast<float2*>(op) = make_float2(ox, oy);
                    __nv_bfloat16 hx = __float2bfloat16(ox);
                    __nv_bfloat16 hy = __float2bfloat16(oy);
                    __nv_bfloat162 hv; hv.x = hx; hv.y = hy;
                    *reinterpret_cast<__nv_bfloat162*>(
                        &g_h_hi[pb1][(size_t)row * H_DIM + col]) = hv;
                    __nv_bfloat162 lv;
                    lv.x = __float2bfloat16(ox - __bfloat162float(hx));
                    lv.y = __float2bfloat16(oy - __bfloat162float(hy));
                    *reinterpret_cast<__nv_bfloat162*>(
                        &g_h_lo[pb1][(size_t)row * H_DIM + col]) = lv;
                }
            }
        }

        // Device-wide step barrier
        if (t + 1 < T_DIM) {
            __syncthreads();
            __threadfence();
            if (tid == 0) {
                atomicAdd(&g_cnt[t], 1);
                volatile int* p = &g_cnt[t];
                while (*p < N_CTAS) { }
            }
            __syncthreads();
            __threadfence();
        }
    }
}

// ---------------------------------------------------------------------------
// Launch
// inputs: 0=x [T,B,IN], 1=h [B,H], 2=Wi_w [H,IN], 3=Wi_b [H],
//         4=Wh_w [H,H], 5=Wh_b [H];  output: hiddens [T,B,H]
// ---------------------------------------------------------------------------
extern "C" void kernel_launch(void* const* d_in, const int* in_sizes, int n_in,
                              void* d_out, int out_size) {
    const float* x   = (const float*)d_in[0];
    const float* h0  = (const float*)d_in[1];
    const float* Wi  = (const float*)d_in[2];
    const float* bi  = (const float*)d_in[3];
    const float* Wh  = (const float*)d_in[4];
    const float* bh  = (const float*)d_in[5];
    float* out = (float*)d_out;

    static bool attr_set = false;
    if (!attr_set) {
        cudaFuncSetAttribute(rnn_hmma,
                             cudaFuncAttributeMaxDynamicSharedMemorySize,
                             SMEM_P2);
        attr_set = true;
    }

    reset_kernel<<<1, 256>>>();
    split_wh_kernel<<<H_DIM * H_DIM / 1024, 256>>>(Wh);
    split_h0_kernel<<<BH / 1024, 256>>>(h0);

    // Phase 1: xi for all timesteps, written straight into d_out
    gemm_xi_kernel<<<dim3(H_DIM / 128, M1 / 128), 256>>>(x, Wi, bi, out);

    // Phase 2: persistent HMMA recurrence (Wh resident in smem)
    rnn_hmma<<<dim3(32, 4), 256, SMEM_P2>>>(bh, out);
}